// round 14
// baseline (speedup 1.0000x reference)
#include <cuda_runtime.h>

#define B_  8
#define H_  8
#define QS_ 64
#define KS_ 512
#define A_  64
#define DH_ 64
#define KC_ 128
#define NC_ 4
#define QD_ 512
#define KD_ 512
#define NF_ 35   // a in [0,NF): FMA-pipe cubic-Newton path; a in [NF,64): MUFU tanh
#define NM_ (A_ - NF_)   // 29 MUFU iterations

typedef unsigned long long ull;

__device__ float g_pout[B_*H_*NC_*QS_*DH_];   // 4 MB
__device__ float g_Sx[B_*H_*NC_*QS_];

__device__ __forceinline__ float fast_tanh(float v) {
    float y; asm("tanh.approx.f32 %0, %1;" : "=f"(y) : "f"(v)); return y;
}
__device__ __forceinline__ ull pk2(float x, float y) {
    ull r; asm("mov.b64 %0, {%1, %2};" : "=l"(r) : "f"(x), "f"(y)); return r;
}
__device__ __forceinline__ float2 upk2(ull v) {
    float2 r; asm("mov.b64 {%0, %1}, %2;" : "=f"(r.x), "=f"(r.y) : "l"(v)); return r;
}
__device__ __forceinline__ ull ffma2(ull a, ull b, ull c) {
    ull d; asm("fma.rn.f32x2 %0, %1, %2, %3;" : "=l"(d) : "l"(a), "l"(b), "l"(c)); return d;
}
__device__ __forceinline__ ull fadd2(ull a, ull b) {
    ull d; asm("add.rn.f32x2 %0, %1, %2;" : "=l"(d) : "l"(a), "l"(b)); return d;
}
// packed fast-reciprocal seed for 1/v given nv = -v (v >= 1):
// seed_int = 0x7EF311C3 - asint(v) = 0xFEF311C3 - asint(nv)  (mod 2^32)
__device__ __forceinline__ ull rcp_seed2(ull nv) {
    unsigned lo, hi;
    asm("mov.b64 {%0, %1}, %2;" : "=r"(lo), "=r"(hi) : "l"(nv));
    lo = 0xFEF311C3u - lo;
    hi = 0xFEF311C3u - hi;
    ull r; asm("mov.b64 %0, {%1, %2};" : "=l"(r) : "r"(lo), "r"(hi));
    return r;
}
#define CP_ASYNC16(dst_u32, src_ptr) \
    asm volatile("cp.async.cg.shared.global [%0], [%1], 16;" \
                 :: "r"(dst_u32), "l"(src_ptr) : "memory")
#define CP_COMMIT()  asm volatile("cp.async.commit_group;" ::: "memory")
#define CP_WAIT0()   asm volatile("cp.async.wait_group 0;" ::: "memory")

// ---------------- smem layout (bytes) — R12/R13 layout, verbatim ----------------
// s_xv @0 f32[128][68]; s_q @34816 f32[64][64] (stride 64, ends 51200);
// s_W1 @51200 f32[64][68]; s_kp @34816 (alias, f32[64][132]);
// s_Wk @68608; s_p @68608 (alias); s_qp @86016 f32[64][68];
// s_bias @103424; s_w2 @103680
#define SMF_BYTES 103936

__global__ void __launch_bounds__(256, 2) fused_kernel(
    const float* __restrict__ x, const float* __restrict__ query,
    const float* __restrict__ W, const float* __restrict__ bias,
    const float* __restrict__ w2, const unsigned char* __restrict__ mask)
{
    extern __shared__ char sm[];
    float* s_xv  = (float*)(sm);
    float* s_q   = (float*)(sm + 34816);
    float* s_W1  = (float*)(sm + 51200);
    float* s_kp  = (float*)(sm + 34816);
    float* s_Wk  = (float*)(sm + 68608);
    float* s_p   = (float*)(sm + 68608);
    float* s_qp  = (float*)(sm + 86016);
    float* s_bias= (float*)(sm + 103424);
    float* s_w2  = (float*)(sm + 103680);

    const int kc = blockIdx.x, h = blockIdx.y, b = blockIdx.z;
    const int tid = threadIdx.x;
    const int tx = tid & 15, ty = tid >> 4;
    const int bh = b * H_ + h;
    const float LOG2E2 = 2.885390082f;   // 2*log2(e)

    const unsigned smb = (unsigned)__cvta_generic_to_shared(sm);

    // ---- t0: async-stage x chunk (K=V) and Wk; they land during the qp GEMM ----
#pragma unroll
    for (int i = 0; i < 8; i++) {
        int idx = tid + 256 * i; int k = idx >> 4, d4 = idx & 15;
        CP_ASYNC16(smb + (k * 68 + d4 * 4) * 4,
                   &x[((size_t)b * KS_ + kc * KC_ + k) * KD_ + h * DH_ + d4 * 4]);
    }
#pragma unroll
    for (int i = 0; i < 4; i++) {
        int idx = tid + 256 * i; int a = idx >> 4, d4 = idx & 15;
        CP_ASYNC16(smb + 68608 + (a * 68 + d4 * 4) * 4,
                   &W[a * 128 + d4 * 4]);
    }
    CP_COMMIT();

    if (tid < 64) { s_bias[tid] = bias[tid]; s_w2[tid] = w2[tid]; }

    // ---- phase 1: stage query [64][64] (stride 64) + Wq ----
#pragma unroll
    for (int i = 0; i < 4; i++) {
        int idx = tid + 256 * i; int q = idx >> 4, d4 = idx & 15;
        *(float4*)&s_q[q * 64 + d4 * 4] =
            *(const float4*)&query[(size_t)(b * QS_ + q) * QD_ + h * DH_ + d4 * 4];
    }
#pragma unroll
    for (int i = 0; i < 4; i++) {
        int idx = tid + 256 * i; int a = idx >> 4, d4 = idx & 15;
        *(float4*)&s_W1[a * 68 + d4 * 4] = *(const float4*)&W[a * 128 + 64 + d4 * 4];
    }
    __syncthreads();

    // ---- qp GEMM (f32x2) -> s_qp[a][q]; a<NF stored as e^{2*qp} ----
    {
        ull acc2[4][4];
#pragma unroll
        for (int i = 0; i < 4; i++)
#pragma unroll
            for (int j = 0; j < 4; j++) acc2[i][j] = 0ULL;
#pragma unroll
        for (int d4 = 0; d4 < 16; d4++) {
            ull wv[4][2];
#pragma unroll
            for (int j = 0; j < 4; j++) {
                float4 v = *(float4*)&s_W1[(tx + 16 * j) * 68 + d4 * 4];
                wv[j][0] = pk2(v.x, v.y); wv[j][1] = pk2(v.z, v.w);
            }
#pragma unroll
            for (int i = 0; i < 4; i++) {
                float4 v = *(float4*)&s_q[(ty * 4 + i) * 64 + d4 * 4];
                ull r0 = pk2(v.x, v.y), r1 = pk2(v.z, v.w);
#pragma unroll
                for (int j = 0; j < 4; j++) {
                    acc2[i][j] = ffma2(r0, wv[j][0], acc2[i][j]);
                    acc2[i][j] = ffma2(r1, wv[j][1], acc2[i][j]);
                }
            }
        }
#pragma unroll
        for (int i = 0; i < 4; i++)
#pragma unroll
            for (int j = 0; j < 4; j++) {
                float2 p = upk2(acc2[i][j]);
                float v = p.x + p.y + s_bias[tx + 16 * j];
                if (tx + 16 * j < NF_) v = exp2f(v * LOG2E2);   // Eq = e^{2*qp}
                s_qp[(tx + 16 * j) * 68 + ty * 4 + i] = v;
            }
    }
    CP_WAIT0();        // x chunk + Wk arrived (this thread's copies)
    __syncthreads();   // visible CTA-wide; also covers s_qp writes

    // ---- kp GEMM (f32x2) -> s_kp[a][k]; a<NF stored as -e^{2*kp} ----
    {
        ull acc2[8][4];
#pragma unroll
        for (int i = 0; i < 8; i++)
#pragma unroll
            for (int j = 0; j < 4; j++) acc2[i][j] = 0ULL;
#pragma unroll
        for (int d4 = 0; d4 < 16; d4++) {
            ull wv[4][2];
#pragma unroll
            for (int j = 0; j < 4; j++) {
                float4 v = *(float4*)&s_Wk[(tx + 16 * j) * 68 + d4 * 4];
                wv[j][0] = pk2(v.x, v.y); wv[j][1] = pk2(v.z, v.w);
            }
#pragma unroll
            for (int i = 0; i < 8; i++) {
                float4 v = *(float4*)&s_xv[(ty * 8 + i) * 68 + d4 * 4];
                ull r0 = pk2(v.x, v.y), r1 = pk2(v.z, v.w);
#pragma unroll
                for (int j = 0; j < 4; j++) {
                    acc2[i][j] = ffma2(r0, wv[j][0], acc2[i][j]);
                    acc2[i][j] = ffma2(r1, wv[j][1], acc2[i][j]);
                }
            }
        }
#pragma unroll
        for (int i = 0; i < 8; i++)
#pragma unroll
            for (int j = 0; j < 4; j++) {
                float2 p = upk2(acc2[i][j]);
                float v = p.x + p.y;
                if (tx + 16 * j < NF_) v = -exp2f(v * LOG2E2);  // Ekn = -e^{2*kp}
                s_kp[(tx + 16 * j) * 132 + ty * 8 + i] = v;
            }
    }
    __syncthreads();

    // ---- phase 3: scores; FMA (a<NF, cubic Newton) and MUFU (a>=NF) interleaved ----
    const int q0 = ty * 4, k0 = tx * 8;
    const ull NEG1_2 = pk2(-1.f, -1.f);
    const ull ONE_2  = pk2(1.f, 1.f);

    float C = 0.f;
#pragma unroll
    for (int a = 0; a < NF_; a++) C += s_w2[a];

    ull acc2[4][4];
#pragma unroll
    for (int j = 0; j < 4; j++)
#pragma unroll
        for (int i = 0; i < 4; i++) acc2[j][i] = pk2(C, C);

#pragma unroll 2
    for (int a2 = 0; a2 < NF_; a2++) {
        // -- FMA path (a = a2): tanh = 1 - 2/(Eq*Ek + 1), cubic compound Newton --
        {
            float4 eq  = *(float4*)&s_qp[a2 * 68 + q0];
            float4 ekA = *(float4*)&s_kp[a2 * 132 + k0];
            float4 ekB = *(float4*)&s_kp[a2 * 132 + k0 + 4];
            ull ek[4] = {pk2(ekA.x, ekA.y), pk2(ekA.z, ekA.w),
                         pk2(ekB.x, ekB.y), pk2(ekB.z, ekB.w)};
            float w2m = -2.f * s_w2[a2];
            ull w22 = pk2(w2m, w2m);
            float eqs[4] = {eq.x, eq.y, eq.z, eq.w};
#pragma unroll
            for (int j = 0; j < 4; j++) {
                ull eqj = pk2(eqs[j], eqs[j]);
#pragma unroll
                for (int i = 0; i < 4; i++) {
                    ull nv = ffma2(eqj, ek[i], NEG1_2);     // -(Eq*Ek + 1)
                    ull r  = rcp_seed2(nv);
                    ull e  = ffma2(nv, r, ONE_2);           // e = 1 - v*r
                    ull t  = ffma2(e, e, e);                // t = e + e^2
                    r = ffma2(r, t, r);                      // r *= (1 + e + e^2): err e^3
                    acc2[j][i] = ffma2(w22, r, acc2[j][i]);  // += w2a*(1-2r)
                }
            }
        }
        // -- MUFU path (a = NF_+a2, NM_ of them): packed args + tanh.approx --
        if (a2 < NM_) {
            int a = NF_ + a2;
            float4 qv = *(float4*)&s_qp[a * 68 + q0];
            float4 kA = *(float4*)&s_kp[a * 132 + k0];
            float4 kB = *(float4*)&s_kp[a * 132 + k0 + 4];
            float w2a = s_w2[a];
            ull w2p = pk2(w2a, w2a);
            ull kp2v[4] = {pk2(kA.x, kA.y), pk2(kA.z, kA.w),
                           pk2(kB.x, kB.y), pk2(kB.z, kB.w)};
            float qs[4] = {qv.x, qv.y, qv.z, qv.w};
#pragma unroll
            for (int j = 0; j < 4; j++) {
                ull qj2 = pk2(qs[j], qs[j]);
#pragma unroll
                for (int i = 0; i < 4; i++) {
                    float2 arg = upk2(fadd2(qj2, kp2v[i]));   // packed q+k
                    float t0 = fast_tanh(arg.x);
                    float t1 = fast_tanh(arg.y);
                    acc2[j][i] = ffma2(w2p, pk2(t0, t1), acc2[j][i]);
                }
            }
        }
    }

    // unpack packed accumulators
    float acc[4][8];
#pragma unroll
    for (int j = 0; j < 4; j++)
#pragma unroll
        for (int i = 0; i < 4; i++) {
            float2 f = upk2(acc2[j][i]);
            acc[j][2 * i] = f.x; acc[j][2 * i + 1] = f.y;
        }

    // ---- phase 4: exp (no max; |score| <= sum|w2|), rowsum, p to smem ----
    float rowsum[4];
    {
        unsigned char mk[8];
        const unsigned char* mrow = &mask[b * KS_ + kc * KC_ + k0];
#pragma unroll
        for (int i = 0; i < 8; i++) mk[i] = mrow[i];
#pragma unroll
        for (int j = 0; j < 4; j++) {
            float s = 0.f;
#pragma unroll
            for (int i = 0; i < 8; i++) {
                float p = mk[i] ? 0.f : __expf(acc[j][i]);
                acc[j][i] = p;
                s += p;
            }
#pragma unroll
            for (int o = 8; o; o >>= 1) s += __shfl_xor_sync(0xffffffffu, s, o);
            rowsum[j] = s;
        }
    }
    __syncthreads();   // phase-3 reads done before p overwrites Wk/qp region

#pragma unroll
    for (int j = 0; j < 4; j++) {
        *(float4*)&s_p[(q0 + j) * 132 + k0]     = make_float4(acc[j][0], acc[j][1], acc[j][2], acc[j][3]);
        *(float4*)&s_p[(q0 + j) * 132 + k0 + 4] = make_float4(acc[j][4], acc[j][5], acc[j][6], acc[j][7]);
    }
    if (tx == 0) {
#pragma unroll
        for (int j = 0; j < 4; j++)
            g_Sx[(bh * NC_ + kc) * QS_ + q0 + j] = rowsum[j];
    }
    __syncthreads();

    // ---- phase 5: partial out = p @ V (4q x 4d per thread) ----
    {
        const int txd = tid & 15, tyq = tid >> 4;
        const int d0 = txd * 4, q0b = tyq * 4;
        ull o2[4][2];
#pragma unroll
        for (int j = 0; j < 4; j++) { o2[j][0] = 0ULL; o2[j][1] = 0ULL; }

#pragma unroll 4
        for (int k = 0; k < KC_; k++) {
            float4 v = *(float4*)&s_xv[k * 68 + d0];
            ull v0 = pk2(v.x, v.y), v1 = pk2(v.z, v.w);
#pragma unroll
            for (int j = 0; j < 4; j++) {
                float p = s_p[(q0b + j) * 132 + k];
                ull p2 = pk2(p, p);
                o2[j][0] = ffma2(p2, v0, o2[j][0]);
                o2[j][1] = ffma2(p2, v1, o2[j][1]);
            }
        }
#pragma unroll
        for (int j = 0; j < 4; j++) {
            float2 a0 = upk2(o2[j][0]), a1 = upk2(o2[j][1]);
            *(float4*)&g_pout[(size_t)((bh * NC_ + kc) * QS_ + q0b + j) * DH_ + d0] =
                make_float4(a0.x, a0.y, a1.x, a1.y);
        }
    }
}

// ---------------- combine: merge 4 chunk partials, 1 float4 per thread ----------------
__global__ void __launch_bounds__(256) combine_kernel(float* __restrict__ out)
{
    const int idx = blockIdx.x * 256 + threadIdx.x;   // 0..1023 per bh
    const int bh = blockIdx.y;
    const int b = bh >> 3, h = bh & 7;
    const int q = idx >> 4, d0 = (idx & 15) * 4;

    float S = 0.f;
#pragma unroll
    for (int c = 0; c < NC_; c++) S += g_Sx[(bh * NC_ + c) * QS_ + q];
    float inv = 1.f / S;

    float4 a = make_float4(0.f, 0.f, 0.f, 0.f);
#pragma unroll
    for (int c = 0; c < NC_; c++) {
        float4 v = *(const float4*)&g_pout[(size_t)((bh * NC_ + c) * QS_ + q) * DH_ + d0];
        a.x += v.x; a.y += v.y; a.z += v.z; a.w += v.w;
    }
    a.x *= inv; a.y *= inv; a.z *= inv; a.w *= inv;

    *(float4*)&out[(size_t)(b * QS_ + q) * QD_ + h * DH_ + d0] = a;
}

// ---------------- launch ----------------
extern "C" void kernel_launch(void* const* d_in, const int* in_sizes, int n_in,
                              void* d_out, int out_size) {
    const float* x     = (const float*)d_in[0];
    const float* query = (const float*)d_in[1];
    const float* W     = (const float*)d_in[2];
    const float* bias  = (const float*)d_in[3];
    const float* w2    = (const float*)d_in[4];
    const unsigned char* mask = (const unsigned char*)d_in[5];
    float* out = (float*)d_out;

    cudaFuncSetAttribute(fused_kernel, cudaFuncAttributeMaxDynamicSharedMemorySize, SMF_BYTES);

    fused_kernel<<<dim3(NC_, H_, B_), 256, SMF_BYTES>>>(x, query, W, bias, w2, mask);
    combine_kernel<<<dim3(4, B_ * H_), 256>>>(out);
}

// round 15
// speedup vs baseline: 1.1696x; 1.1696x over previous
#include <cuda_runtime.h>

#define B_  8
#define H_  8
#define QS_ 64
#define KS_ 512
#define A_  64
#define DH_ 64
#define KC_ 128
#define NC_ 4
#define QD_ 512
#define KD_ 512
#define NF_ 35   // a in [0,NF): FMA-pipe cubic-Newton path; a in [NF,64): MUFU tanh
#define NM_ (A_ - NF_)

typedef unsigned long long ull;

__device__ float g_pout[B_*H_*NC_*QS_*DH_];   // 4 MB
__device__ float g_Sx[B_*H_*NC_*QS_];

__device__ __forceinline__ float fast_tanh(float v) {
    float y; asm("tanh.approx.f32 %0, %1;" : "=f"(y) : "f"(v)); return y;
}
__device__ __forceinline__ ull pk2(float x, float y) {
    ull r; asm("mov.b64 %0, {%1, %2};" : "=l"(r) : "f"(x), "f"(y)); return r;
}
__device__ __forceinline__ float2 upk2(ull v) {
    float2 r; asm("mov.b64 {%0, %1}, %2;" : "=f"(r.x), "=f"(r.y) : "l"(v)); return r;
}
__device__ __forceinline__ ull ffma2(ull a, ull b, ull c) {
    ull d; asm("fma.rn.f32x2 %0, %1, %2, %3;" : "=l"(d) : "l"(a), "l"(b), "l"(c)); return d;
}
__device__ __forceinline__ ull fadd2(ull a, ull b) {
    ull d; asm("add.rn.f32x2 %0, %1, %2;" : "=l"(d) : "l"(a), "l"(b)); return d;
}
__device__ __forceinline__ ull rcp_seed2(ull nv) {
    unsigned lo, hi;
    asm("mov.b64 {%0, %1}, %2;" : "=r"(lo), "=r"(hi) : "l"(nv));
    lo = 0xFEF311C3u - lo;
    hi = 0xFEF311C3u - hi;
    ull r; asm("mov.b64 %0, {%1, %2};" : "=l"(r) : "r"(lo), "r"(hi));
    return r;
}
__device__ __forceinline__ unsigned tf32c(float f) {
    unsigned r; asm("cvt.rna.tf32.f32 %0, %1;" : "=r"(r) : "f"(f)); return r;
}
__device__ __forceinline__ void mma_tf32(float* d, const unsigned* a, const unsigned* b) {
    asm volatile("mma.sync.aligned.m16n8k8.row.col.f32.tf32.tf32.f32 "
        "{%0,%1,%2,%3}, {%4,%5,%6,%7}, {%8,%9}, {%0,%1,%2,%3};"
        : "+f"(d[0]), "+f"(d[1]), "+f"(d[2]), "+f"(d[3])
        : "r"(a[0]), "r"(a[1]), "r"(a[2]), "r"(a[3]), "r"(b[0]), "r"(b[1]));
}

// ---------------- smem layout (bytes) — R12/R13 layout, verbatim ----------------
// s_xv @0 f32[128][68]; s_q @34816 f32[64][64] (stride 64, ends 51200);
// s_W1 @51200 f32[64][68]; s_kp @34816 (alias, f32[64][132]);
// s_Wk @68608; s_p @68608 (alias, f32[64][132]); s_qp @86016 f32[64][68];
// s_bias @103424; s_w2 @103680
#define SMF_BYTES 103936

__global__ void __launch_bounds__(256, 2) fused_kernel(
    const float* __restrict__ x, const float* __restrict__ query,
    const float* __restrict__ W, const float* __restrict__ bias,
    const float* __restrict__ w2, const unsigned char* __restrict__ mask)
{
    extern __shared__ char sm[];
    float* s_xv  = (float*)(sm);
    float* s_q   = (float*)(sm + 34816);
    float* s_W1  = (float*)(sm + 51200);
    float* s_kp  = (float*)(sm + 34816);
    float* s_Wk  = (float*)(sm + 68608);
    float* s_p   = (float*)(sm + 68608);
    float* s_qp  = (float*)(sm + 86016);
    float* s_bias= (float*)(sm + 103424);
    float* s_w2  = (float*)(sm + 103680);

    const int kc = blockIdx.x, h = blockIdx.y, b = blockIdx.z;
    const int tid = threadIdx.x;
    const int tx = tid & 15, ty = tid >> 4;
    const int warp = tid >> 5, lane = tid & 31;
    const int grp = lane >> 2, thr = lane & 3;
    const int bh = b * H_ + h;
    const float LOG2E2 = 2.885390082f;   // 2*log2(e)

    if (tid < 64) { s_bias[tid] = bias[tid]; s_w2[tid] = w2[tid]; }

    // ---- phase 1: stage query [64][64] (stride 64) + Wq ----
#pragma unroll
    for (int i = 0; i < 4; i++) {
        int idx = tid + 256 * i; int q = idx >> 4, d4 = idx & 15;
        *(float4*)&s_q[q * 64 + d4 * 4] =
            *(const float4*)&query[(size_t)(b * QS_ + q) * QD_ + h * DH_ + d4 * 4];
    }
#pragma unroll
    for (int i = 0; i < 4; i++) {
        int idx = tid + 256 * i; int a = idx >> 4, d4 = idx & 15;
        *(float4*)&s_W1[a * 68 + d4 * 4] = *(const float4*)&W[a * 128 + 64 + d4 * 4];
    }
    __syncthreads();

    // ---- qp via TF32 MMA: out[q=64][a=64] = q[64][d64] . Wq[a][d64]^T ----
    // warp w: q rows 16*(w&3).. , a cols 32*(w>>2).. (4 n8-tiles), 8 k8-steps
    {
        const int qr0 = 16 * (warp & 3), ac0 = 32 * (warp >> 2);
        float c[4][4];
#pragma unroll
        for (int nt = 0; nt < 4; nt++)
#pragma unroll
            for (int r = 0; r < 4; r++) c[nt][r] = 0.f;
#pragma unroll
        for (int kk = 0; kk < 8; kk++) {
            int d0 = kk * 8;
            unsigned A[4];
            A[0] = tf32c(s_q[(qr0 + grp) * 64 + d0 + thr]);
            A[1] = tf32c(s_q[(qr0 + grp + 8) * 64 + d0 + thr]);
            A[2] = tf32c(s_q[(qr0 + grp) * 64 + d0 + thr + 4]);
            A[3] = tf32c(s_q[(qr0 + grp + 8) * 64 + d0 + thr + 4]);
#pragma unroll
            for (int nt = 0; nt < 4; nt++) {
                unsigned Bf[2];
                Bf[0] = tf32c(s_W1[(ac0 + nt * 8 + grp) * 68 + d0 + thr]);
                Bf[1] = tf32c(s_W1[(ac0 + nt * 8 + grp) * 68 + d0 + thr + 4]);
                mma_tf32(c[nt], A, Bf);
            }
        }
        __syncthreads();   // all reads of s_q/s_W1 done before qp writes? (s_qp separate)
        // epilogue: c[nt][0]:(q=qr0+grp, a=ac0+8nt+2thr); [1]:a+1; [2]:q+8; [3]:q+8,a+1
#pragma unroll
        for (int nt = 0; nt < 4; nt++) {
            int a0 = ac0 + nt * 8 + 2 * thr;
#pragma unroll
            for (int r = 0; r < 4; r++) {
                int aa = a0 + (r & 1);
                int qq = qr0 + grp + (r >= 2 ? 8 : 0);
                float v = c[nt][r] + s_bias[aa];
                if (aa < NF_) v = exp2f(v * LOG2E2);    // Eq = e^{2*qp}
                s_qp[aa * 68 + qq] = v;
            }
        }
    }
    __syncthreads();

    // ---- phase 2: stage x chunk [128][68] + Wk ----
#pragma unroll
    for (int i = 0; i < 8; i++) {
        int idx = tid + 256 * i; int k = idx >> 4, d4 = idx & 15;
        *(float4*)&s_xv[k * 68 + d4 * 4] =
            *(const float4*)&x[((size_t)b * KS_ + kc * KC_ + k) * KD_ + h * DH_ + d4 * 4];
    }
#pragma unroll
    for (int i = 0; i < 4; i++) {
        int idx = tid + 256 * i; int a = idx >> 4, d4 = idx & 15;
        *(float4*)&s_Wk[a * 68 + d4 * 4] = *(const float4*)&W[a * 128 + d4 * 4];
    }
    __syncthreads();

    // ---- kp via TF32 MMA: out[k=128][a=64] = x[k][d64] . Wk[a][d64]^T ----
    // warp w: k rows 16*w.., full a width (8 n8-tiles), 8 k8-steps
    {
        const int kr0 = 16 * warp;
        float c[8][4];
#pragma unroll
        for (int nt = 0; nt < 8; nt++)
#pragma unroll
            for (int r = 0; r < 4; r++) c[nt][r] = 0.f;
#pragma unroll
        for (int kk = 0; kk < 8; kk++) {
            int d0 = kk * 8;
            unsigned A[4];
            A[0] = tf32c(s_xv[(kr0 + grp) * 68 + d0 + thr]);
            A[1] = tf32c(s_xv[(kr0 + grp + 8) * 68 + d0 + thr]);
            A[2] = tf32c(s_xv[(kr0 + grp) * 68 + d0 + thr + 4]);
            A[3] = tf32c(s_xv[(kr0 + grp + 8) * 68 + d0 + thr + 4]);
#pragma unroll
            for (int nt = 0; nt < 8; nt++) {
                unsigned Bf[2];
                Bf[0] = tf32c(s_Wk[(nt * 8 + grp) * 68 + d0 + thr]);
                Bf[1] = tf32c(s_Wk[(nt * 8 + grp) * 68 + d0 + thr + 4]);
                mma_tf32(c[nt], A, Bf);
            }
        }
        __syncthreads();   // s_q region (= s_kp dest) fully dead; Wk reads done CTA-wide
#pragma unroll
        for (int nt = 0; nt < 8; nt++) {
            int a0 = nt * 8 + 2 * thr;
#pragma unroll
            for (int r = 0; r < 4; r++) {
                int aa = a0 + (r & 1);
                int kk2 = kr0 + grp + (r >= 2 ? 8 : 0);
                float v = c[nt][r];
                if (aa < NF_) v = -exp2f(v * LOG2E2);   // Ekn = -e^{2*kp}
                s_kp[aa * 132 + kk2] = v;
            }
        }
    }
    __syncthreads();

    // ---- phase 3: scores; FMA (a<NF, cubic Newton) and MUFU (a>=NF) interleaved ----
    const int q0 = ty * 4, k0 = tx * 8;
    const ull NEG1_2 = pk2(-1.f, -1.f);
    const ull ONE_2  = pk2(1.f, 1.f);

    float C = 0.f;
#pragma unroll
    for (int a = 0; a < NF_; a++) C += s_w2[a];

    ull acc2[4][4];
#pragma unroll
    for (int j = 0; j < 4; j++)
#pragma unroll
        for (int i = 0; i < 4; i++) acc2[j][i] = pk2(C, C);

#pragma unroll 2
    for (int a2 = 0; a2 < NF_; a2++) {
        {
            float4 eq  = *(float4*)&s_qp[a2 * 68 + q0];
            float4 ekA = *(float4*)&s_kp[a2 * 132 + k0];
            float4 ekB = *(float4*)&s_kp[a2 * 132 + k0 + 4];
            ull ek[4] = {pk2(ekA.x, ekA.y), pk2(ekA.z, ekA.w),
                         pk2(ekB.x, ekB.y), pk2(ekB.z, ekB.w)};
            float w2m = -2.f * s_w2[a2];
            ull w22 = pk2(w2m, w2m);
            float eqs[4] = {eq.x, eq.y, eq.z, eq.w};
#pragma unroll
            for (int j = 0; j < 4; j++) {
                ull eqj = pk2(eqs[j], eqs[j]);
#pragma unroll
                for (int i = 0; i < 4; i++) {
                    ull nv = ffma2(eqj, ek[i], NEG1_2);     // -(Eq*Ek + 1)
                    ull r  = rcp_seed2(nv);
                    ull e  = ffma2(nv, r, ONE_2);           // e = 1 - v*r
                    ull t  = ffma2(e, e, e);                // t = e + e^2
                    r = ffma2(r, t, r);                      // cubic Newton
                    acc2[j][i] = ffma2(w22, r, acc2[j][i]);
                }
            }
        }
        if (a2 < NM_) {
            int a = NF_ + a2;
            float4 qv = *(float4*)&s_qp[a * 68 + q0];
            float4 kA = *(float4*)&s_kp[a * 132 + k0];
            float4 kB = *(float4*)&s_kp[a * 132 + k0 + 4];
            float w2a = s_w2[a];
            ull w2p = pk2(w2a, w2a);
            ull kp2v[4] = {pk2(kA.x, kA.y), pk2(kA.z, kA.w),
                           pk2(kB.x, kB.y), pk2(kB.z, kB.w)};
            float qs[4] = {qv.x, qv.y, qv.z, qv.w};
#pragma unroll
            for (int j = 0; j < 4; j++) {
                ull qj2 = pk2(qs[j], qs[j]);
#pragma unroll
                for (int i = 0; i < 4; i++) {
                    float2 arg = upk2(fadd2(qj2, kp2v[i]));
                    float t0 = fast_tanh(arg.x);
                    float t1 = fast_tanh(arg.y);
                    acc2[j][i] = ffma2(w2p, pk2(t0, t1), acc2[j][i]);
                }
            }
        }
    }

    float acc[4][8];
#pragma unroll
    for (int j = 0; j < 4; j++)
#pragma unroll
        for (int i = 0; i < 4; i++) {
            float2 f = upk2(acc2[j][i]);
            acc[j][2 * i] = f.x; acc[j][2 * i + 1] = f.y;
        }

    // ---- phase 4: exp (no max), rowsum, p to smem ----
    float rowsum[4];
    {
        unsigned char mk[8];
        const unsigned char* mrow = &mask[b * KS_ + kc * KC_ + k0];
#pragma unroll
        for (int i = 0; i < 8; i++) mk[i] = mrow[i];
#pragma unroll
        for (int j = 0; j < 4; j++) {
            float s = 0.f;
#pragma unroll
            for (int i = 0; i < 8; i++) {
                float p = mk[i] ? 0.f : __expf(acc[j][i]);
                acc[j][i] = p;
                s += p;
            }
#pragma unroll
            for (int o = 8; o; o >>= 1) s += __shfl_xor_sync(0xffffffffu, s, o);
            rowsum[j] = s;
        }
    }
    __syncthreads();   // tanh reads of s_kp/s_qp done before p overwrites the region

#pragma unroll
    for (int j = 0; j < 4; j++) {
        *(float4*)&s_p[(q0 + j) * 132 + k0]     = make_float4(acc[j][0], acc[j][1], acc[j][2], acc[j][3]);
        *(float4*)&s_p[(q0 + j) * 132 + k0 + 4] = make_float4(acc[j][4], acc[j][5], acc[j][6], acc[j][7]);
    }
    if (tx == 0) {
#pragma unroll
        for (int j = 0; j < 4; j++)
            g_Sx[(bh * NC_ + kc) * QS_ + q0 + j] = rowsum[j];
    }
    __syncthreads();

    // ---- phase 5: pV via TF32 MMA: out[q=64][d=64] = p[q][k128] . V[k][d] ----
    // warp w: q rows 16*(w&3).., d cols 32*(w>>2).. (4 n8-tiles), 16 k8-steps
    {
        const int qr0 = 16 * (warp & 3), dc0 = 32 * (warp >> 2);
        float c[4][4];
#pragma unroll
        for (int nt = 0; nt < 4; nt++)
#pragma unroll
            for (int r = 0; r < 4; r++) c[nt][r] = 0.f;
#pragma unroll
        for (int kk = 0; kk < 16; kk++) {
            int kb = kk * 8;
            unsigned A[4];
            A[0] = tf32c(s_p[(qr0 + grp) * 132 + kb + thr]);
            A[1] = tf32c(s_p[(qr0 + grp + 8) * 132 + kb + thr]);
            A[2] = tf32c(s_p[(qr0 + grp) * 132 + kb + thr + 4]);
            A[3] = tf32c(s_p[(qr0 + grp + 8) * 132 + kb + thr + 4]);
#pragma unroll
            for (int nt = 0; nt < 4; nt++) {
                unsigned Bf[2];
                Bf[0] = tf32c(s_xv[(kb + thr) * 68 + dc0 + nt * 8 + grp]);
                Bf[1] = tf32c(s_xv[(kb + thr + 4) * 68 + dc0 + nt * 8 + grp]);
                mma_tf32(c[nt], A, Bf);
            }
        }
        const int pp = bh * NC_ + kc;
#pragma unroll
        for (int nt = 0; nt < 4; nt++) {
            int d0 = dc0 + nt * 8 + 2 * thr;
            int qa = qr0 + grp;
            *(float2*)&g_pout[(size_t)(pp * QS_ + qa) * DH_ + d0]     = make_float2(c[nt][0], c[nt][1]);
            *(float2*)&g_pout[(size_t)(pp * QS_ + qa + 8) * DH_ + d0] = make_float2(c[nt][2], c[nt][3]);
        }
    }
}

// ---------------- combine: merge 4 chunk partials, 1 float4 per thread ----------------
__global__ void __launch_bounds__(256) combine_kernel(float* __restrict__ out)
{
    const int idx = blockIdx.x * 256 + threadIdx.x;
    const int bh = blockIdx.y;
    const int b = bh >> 3, h = bh & 7;
    const int q = idx >> 4, d0 = (idx & 15) * 4;

    float S = 0.f;
#pragma unroll
    for (int c = 0; c < NC_; c++) S += g_Sx[(bh * NC_ + c) * QS_ + q];
    float inv = 1.f / S;

    float4 a = make_float4(0.f, 0.f, 0.f, 0.f);
#pragma unroll
    for (int c = 0; c < NC_; c++) {
        float4 v = *(const float4*)&g_pout[(size_t)((bh * NC_ + c) * QS_ + q) * DH_ + d0];
        a.x += v.x; a.y += v.y; a.z += v.z; a.w += v.w;
    }
    a.x *= inv; a.y *= inv; a.z *= inv; a.w *= inv;

    *(float4*)&out[(size_t)(b * QS_ + q) * QD_ + h * DH_ + d0] = a;
}

// ---------------- launch ----------------
extern "C" void kernel_launch(void* const* d_in, const int* in_sizes, int n_in,
                              void* d_out, int out_size) {
    const float* x     = (const float*)d_in[0];
    const float* query = (const float*)d_in[1];
    const float* W     = (const float*)d_in[2];
    const float* bias  = (const float*)d_in[3];
    const float* w2    = (const float*)d_in[4];
    const unsigned char* mask = (const unsigned char*)d_in[5];
    float* out = (float*)d_out;

    cudaFuncSetAttribute(fused_kernel, cudaFuncAttributeMaxDynamicSharedMemorySize, SMF_BYTES);

    fused_kernel<<<dim3(NC_, H_, B_), 256, SMF_BYTES>>>(x, query, W, bias, w2, mask);
    combine_kernel<<<dim3(4, B_ * H_), 256>>>(out);
}